// round 2
// baseline (speedup 1.0000x reference)
#include <cuda_runtime.h>
#include <math.h>

// Problem constants
#define B_   64
#define T_   512
#define I_   256
#define D_   1024
#define M_   128              // fwd(64) + bwd(64) stacked rows

// Scratch (device globals: allocation-free)
__device__ float g_E[T_ * B_ * D_];      // embed, layout [t][b][d]  (134 MB)
__device__ float g_carry[2][M_ * D_];    // ping-pong carries (128 x 1024 each)
__device__ float g_sfin[M_ * D_];        // final post-erf states

// ---------------------------------------------------------------------------
// Zero the initial carry buffer
// ---------------------------------------------------------------------------
__global__ void zero_carry_kernel() {
    int idx = blockIdx.x * blockDim.x + threadIdx.x;   // 512*256 = 131072 threads
    g_carry[0][idx] = 0.0f;
}

// ---------------------------------------------------------------------------
// Embed: E[t][b][d] = dot(inp[b,t,:], U[:,d]) / 16 + bias[d]
// Tile: 64 rows (= all b for one t) x 64 cols, BK=32, 256 threads, 4x4 micro.
// grid = (16, 512)
// ---------------------------------------------------------------------------
__global__ void embed_kernel(const float* __restrict__ inp,
                             const float* __restrict__ U,
                             const float* __restrict__ bias) {
    __shared__ float AsT[32][68];   // [k][row], padded
    __shared__ float Bs[32][68];    // [k][n],  padded

    const int tid = threadIdx.x;
    const int t   = blockIdx.y;     // 0..511
    const int nb  = blockIdx.x;     // 0..15
    const int tx  = tid & 15;       // col group (4 cols)
    const int ty  = tid >> 4;       // row group (4 rows)
    const int n0  = nb * 64;

    float4 acc0 = {0,0,0,0}, acc1 = {0,0,0,0}, acc2 = {0,0,0,0}, acc3 = {0,0,0,0};

    for (int k0 = 0; k0 < I_; k0 += 32) {
        __syncthreads();
        // A tile: 64 (b) x 32 (i) -> transposed into AsT[k][row]
        #pragma unroll
        for (int i = 0; i < 2; i++) {
            int idx = i * 256 + tid;
            int r   = idx >> 3;        // batch row 0..63
            int c4  = idx & 7;         // float4 within 32-wide k chunk
            float4 a = *(const float4*)&inp[((size_t)r * T_ + t) * I_ + k0 + c4 * 4];
            AsT[c4 * 4 + 0][r] = a.x;
            AsT[c4 * 4 + 1][r] = a.y;
            AsT[c4 * 4 + 2][r] = a.z;
            AsT[c4 * 4 + 3][r] = a.w;
        }
        // B tile: 32 (k) x 64 (n)
        #pragma unroll
        for (int i = 0; i < 2; i++) {
            int idx = i * 256 + tid;
            int r   = idx >> 4;        // k row 0..31
            int c4  = idx & 15;
            *(float4*)&Bs[r][c4 * 4] =
                *(const float4*)&U[(size_t)(k0 + r) * D_ + n0 + c4 * 4];
        }
        __syncthreads();
        #pragma unroll
        for (int k = 0; k < 32; k++) {
            float4 a = *(const float4*)&AsT[k][ty * 4];
            float4 w = *(const float4*)&Bs[k][tx * 4];
            acc0.x += a.x * w.x; acc0.y += a.x * w.y; acc0.z += a.x * w.z; acc0.w += a.x * w.w;
            acc1.x += a.y * w.x; acc1.y += a.y * w.y; acc1.z += a.y * w.z; acc1.w += a.y * w.w;
            acc2.x += a.z * w.x; acc2.y += a.z * w.y; acc2.z += a.z * w.z; acc2.w += a.z * w.w;
            acc3.x += a.w * w.x; acc3.y += a.w * w.y; acc3.z += a.w * w.z; acc3.w += a.w * w.w;
        }
    }

    const int n = n0 + tx * 4;
    float4 bv = *(const float4*)&bias[n];
    const float inv16 = 0.0625f;
    float4 o;
    int b;

    b = ty * 4 + 0;
    o.x = acc0.x * inv16 + bv.x; o.y = acc0.y * inv16 + bv.y;
    o.z = acc0.z * inv16 + bv.z; o.w = acc0.w * inv16 + bv.w;
    *(float4*)&g_E[(size_t)t * (B_ * D_) + b * D_ + n] = o;

    b = ty * 4 + 1;
    o.x = acc1.x * inv16 + bv.x; o.y = acc1.y * inv16 + bv.y;
    o.z = acc1.z * inv16 + bv.z; o.w = acc1.w * inv16 + bv.w;
    *(float4*)&g_E[(size_t)t * (B_ * D_) + b * D_ + n] = o;

    b = ty * 4 + 2;
    o.x = acc2.x * inv16 + bv.x; o.y = acc2.y * inv16 + bv.y;
    o.z = acc2.z * inv16 + bv.z; o.w = acc2.w * inv16 + bv.w;
    *(float4*)&g_E[(size_t)t * (B_ * D_) + b * D_ + n] = o;

    b = ty * 4 + 3;
    o.x = acc3.x * inv16 + bv.x; o.y = acc3.y * inv16 + bv.y;
    o.z = acc3.z * inv16 + bv.z; o.w = acc3.w * inv16 + bv.w;
    *(float4*)&g_E[(size_t)t * (B_ * D_) + b * D_ + n] = o;
}

// ---------------------------------------------------------------------------
// One recurrence step:
//   s   = erf(E_t + c_in)        (rows 0..63 use E[t], rows 64..127 use E[511-t])
//   c_out = s @ W / 32
// Tile: 16 (M) x 64 (N), K staged 64 at a time. grid = (16, 8), 256 threads.
// ---------------------------------------------------------------------------
__global__ void step_kernel(const float* __restrict__ W, int t, int pin, int pout) {
    __shared__ float Ss[16][68];    // s tile   [m-local][k-local], padded
    __shared__ float Ws[64][68];    // W tile   [k-local][n-local], padded

    const float* __restrict__ cin = g_carry[pin];
    float* __restrict__ cout      = g_carry[pout];

    const int tid = threadIdx.x;
    const int tx  = tid & 15;       // col group: cols n0 + tx*4 .. +3
    const int ty  = tid >> 4;       // row 0..15
    const int mb  = blockIdx.y;     // 0..7
    const int nb  = blockIdx.x;     // 0..15
    const int n0  = nb * 64;

    float4 acc = {0.f, 0.f, 0.f, 0.f};

    for (int k0 = 0; k0 < D_; k0 += 64) {
        __syncthreads();
        // Stage s tile: 16 rows x 64 k, fused erf(E + c)
        #pragma unroll
        for (int i = 0; i < 4; i++) {
            int idx = i * 256 + tid;
            int r   = idx >> 6;             // 0..15
            int c   = idx & 63;
            int m   = mb * 16 + r;          // global row 0..127
            int col = k0 + c;
            float e;
            if (m < B_)
                e = g_E[(size_t)t * (B_ * D_) + m * D_ + col];
            else
                e = g_E[(size_t)(T_ - 1 - t) * (B_ * D_) + (m - B_) * D_ + col];
            Ss[r][c] = erff(e + cin[m * D_ + col]);
        }
        // Stage W tile: 64 k x 64 n
        #pragma unroll
        for (int i = 0; i < 4; i++) {
            int idx = i * 256 + tid;
            int r   = idx >> 4;             // 0..63
            int c4  = idx & 15;
            *(float4*)&Ws[r][c4 * 4] =
                *(const float4*)&W[(size_t)(k0 + r) * D_ + n0 + c4 * 4];
        }
        __syncthreads();

        #pragma unroll
        for (int k = 0; k < 64; k += 4) {
            float4 a = *(const float4*)&Ss[ty][k];
            float4 w;
            w = *(const float4*)&Ws[k + 0][tx * 4];
            acc.x += a.x * w.x; acc.y += a.x * w.y; acc.z += a.x * w.z; acc.w += a.x * w.w;
            w = *(const float4*)&Ws[k + 1][tx * 4];
            acc.x += a.y * w.x; acc.y += a.y * w.y; acc.z += a.y * w.z; acc.w += a.y * w.w;
            w = *(const float4*)&Ws[k + 2][tx * 4];
            acc.x += a.z * w.x; acc.y += a.z * w.y; acc.z += a.z * w.z; acc.w += a.z * w.w;
            w = *(const float4*)&Ws[k + 3][tx * 4];
            acc.x += a.w * w.x; acc.y += a.w * w.y; acc.z += a.w * w.z; acc.w += a.w * w.w;
        }
    }

    const float inv32 = 0.03125f;
    const int m = mb * 16 + ty;
    float4 o;
    o.x = acc.x * inv32; o.y = acc.y * inv32; o.z = acc.z * inv32; o.w = acc.w * inv32;
    *(float4*)&cout[m * D_ + n0 + tx * 4] = o;
}

// ---------------------------------------------------------------------------
// Final state: s = erf(E_{511}/E_0 + carry)   (no W transform on last step)
// ---------------------------------------------------------------------------
__global__ void sfinal_kernel(int pin) {
    const float* __restrict__ cin = g_carry[pin];
    int idx = blockIdx.x * blockDim.x + threadIdx.x;   // 0..131071
    int m = idx >> 10;
    int d = idx & 1023;
    float e;
    if (m < B_)
        e = g_E[(size_t)(T_ - 1) * (B_ * D_) + m * D_ + d];
    else
        e = g_E[(size_t)0 * (B_ * D_) + (m - B_) * D_ + d];
    g_sfin[idx] = erff(e + cin[idx]);
}

// ---------------------------------------------------------------------------
// Output: out[b] = (sum_d sf[b][d]*v[d] + sb[b][d]*v[1024+d]) / 32
// grid = 64 blocks (one per batch row), 256 threads
// ---------------------------------------------------------------------------
__global__ void out_kernel(const float* __restrict__ v, float* __restrict__ out) {
    const int b   = blockIdx.x;
    const int tid = threadIdx.x;
    float sum = 0.f;
    for (int d = tid; d < D_; d += 256) {
        sum += g_sfin[b * D_ + d] * v[d];
        sum += g_sfin[(B_ + b) * D_ + d] * v[D_ + d];
    }
    __shared__ float red[256];
    red[tid] = sum;
    __syncthreads();
    #pragma unroll
    for (int s = 128; s > 0; s >>= 1) {
        if (tid < s) red[tid] += red[tid + s];
        __syncthreads();
    }
    if (tid == 0) out[b] = red[0] * 0.03125f;
}

// ---------------------------------------------------------------------------
// kernel_launch: graph-capturable (kernel launches only)
// ---------------------------------------------------------------------------
extern "C" void kernel_launch(void* const* d_in, const int* in_sizes, int n_in,
                              void* d_out, int out_size) {
    const float* inp  = (const float*)d_in[0];   // (64, 512, 256)
    const float* W    = (const float*)d_in[1];   // (1024, 1024)
    const float* U    = (const float*)d_in[2];   // (256, 1024)
    const float* bias = (const float*)d_in[3];   // (1024,)
    const float* v    = (const float*)d_in[4];   // (2048, 1)
    float* out        = (float*)d_out;           // (64, 1)

    // init carry[0] = 0
    zero_carry_kernel<<<512, 256>>>();

    // embed: E[t][b][d]
    embed_kernel<<<dim3(16, T_), 256>>>(inp, U, bias);

    // recurrence: 511 full steps (last step applies erf only, no W)
    for (int t = 0; t < T_ - 1; t++) {
        step_kernel<<<dim3(16, 8), 256>>>(W, t, t & 1, (t + 1) & 1);
    }

    // final post-erf states (reads carry after step 510 -> buffer (511 & 1) = 1)
    sfinal_kernel<<<512, 256>>>((T_ - 1) & 1);

    // classifier head
    out_kernel<<<B_, 256>>>(v, out);
}

// round 3
// speedup vs baseline: 1.4216x; 1.4216x over previous
#include <cuda_runtime.h>
#include <math.h>

// Problem constants
#define B_   64
#define T_   512
#define I_   256
#define D_   1024
#define M_   128              // fwd(64) + bwd(64) stacked rows

// Scratch (device globals: allocation-free)
__device__ float g_E[T_ * B_ * D_];      // embed, layout [t][b][d]
__device__ float g_s[2][M_ * D_];        // ping-pong post-erf states s_t

// ---------------------------------------------------------------------------
// Embed: E[t][b][d] = dot(inp[b,t,:], U[:,d]) / 16 + bias[d]
// grid = (16, 512), 256 threads, 64x64 tile, BK=32
// ---------------------------------------------------------------------------
__global__ void embed_kernel(const float* __restrict__ inp,
                             const float* __restrict__ U,
                             const float* __restrict__ bias) {
    __shared__ float AsT[32][68];   // [k][row], padded
    __shared__ float Bs[32][68];    // [k][n],  padded

    const int tid = threadIdx.x;
    const int t   = blockIdx.y;
    const int nb  = blockIdx.x;
    const int tx  = tid & 15;
    const int ty  = tid >> 4;
    const int n0  = nb * 64;

    float4 acc0 = {0,0,0,0}, acc1 = {0,0,0,0}, acc2 = {0,0,0,0}, acc3 = {0,0,0,0};

    for (int k0 = 0; k0 < I_; k0 += 32) {
        __syncthreads();
        #pragma unroll
        for (int i = 0; i < 2; i++) {
            int idx = i * 256 + tid;
            int r   = idx >> 3;
            int c4  = idx & 7;
            float4 a = *(const float4*)&inp[((size_t)r * T_ + t) * I_ + k0 + c4 * 4];
            AsT[c4 * 4 + 0][r] = a.x;
            AsT[c4 * 4 + 1][r] = a.y;
            AsT[c4 * 4 + 2][r] = a.z;
            AsT[c4 * 4 + 3][r] = a.w;
        }
        #pragma unroll
        for (int i = 0; i < 2; i++) {
            int idx = i * 256 + tid;
            int r   = idx >> 4;
            int c4  = idx & 15;
            *(float4*)&Bs[r][c4 * 4] =
                *(const float4*)&U[(size_t)(k0 + r) * D_ + n0 + c4 * 4];
        }
        __syncthreads();
        #pragma unroll
        for (int k = 0; k < 32; k++) {
            float4 a = *(const float4*)&AsT[k][ty * 4];
            float4 w = *(const float4*)&Bs[k][tx * 4];
            acc0.x += a.x * w.x; acc0.y += a.x * w.y; acc0.z += a.x * w.z; acc0.w += a.x * w.w;
            acc1.x += a.y * w.x; acc1.y += a.y * w.y; acc1.z += a.y * w.z; acc1.w += a.y * w.w;
            acc2.x += a.z * w.x; acc2.y += a.z * w.y; acc2.z += a.z * w.z; acc2.w += a.z * w.w;
            acc3.x += a.w * w.x; acc3.y += a.w * w.y; acc3.z += a.w * w.z; acc3.w += a.w * w.w;
        }
    }

    const int n = n0 + tx * 4;
    float4 bv = *(const float4*)&bias[n];
    const float inv16 = 0.0625f;
    float4 o;
    int b;

    b = ty * 4 + 0;
    o.x = acc0.x * inv16 + bv.x; o.y = acc0.y * inv16 + bv.y;
    o.z = acc0.z * inv16 + bv.z; o.w = acc0.w * inv16 + bv.w;
    *(float4*)&g_E[(size_t)t * (B_ * D_) + b * D_ + n] = o;

    b = ty * 4 + 1;
    o.x = acc1.x * inv16 + bv.x; o.y = acc1.y * inv16 + bv.y;
    o.z = acc1.z * inv16 + bv.z; o.w = acc1.w * inv16 + bv.w;
    *(float4*)&g_E[(size_t)t * (B_ * D_) + b * D_ + n] = o;

    b = ty * 4 + 2;
    o.x = acc2.x * inv16 + bv.x; o.y = acc2.y * inv16 + bv.y;
    o.z = acc2.z * inv16 + bv.z; o.w = acc2.w * inv16 + bv.w;
    *(float4*)&g_E[(size_t)t * (B_ * D_) + b * D_ + n] = o;

    b = ty * 4 + 3;
    o.x = acc3.x * inv16 + bv.x; o.y = acc3.y * inv16 + bv.y;
    o.z = acc3.z * inv16 + bv.z; o.w = acc3.w * inv16 + bv.w;
    *(float4*)&g_E[(size_t)t * (B_ * D_) + b * D_ + n] = o;
}

// ---------------------------------------------------------------------------
// Initial state: s_0 = erf(E[0]) for fwd rows, erf(E[T-1]) for bwd rows
// ---------------------------------------------------------------------------
__global__ void s0_kernel() {
    int idx = blockIdx.x * blockDim.x + threadIdx.x;   // 0..131071
    int m = idx >> 10;
    int d = idx & 1023;
    float e;
    if (m < B_)
        e = g_E[(size_t)0 * (B_ * D_) + m * D_ + d];
    else
        e = g_E[(size_t)(T_ - 1) * (B_ * D_) + (m - B_) * D_ + d];
    g_s[0][idx] = erff(e);
}

// ---------------------------------------------------------------------------
// One recurrence step (pure GEMM mainloop + erf epilogue):
//   c      = s_t @ W / 32
//   s_{t+1} = erf(E[te] + c)      (te = te_f for fwd rows, te_b for bwd rows)
// Tile: 16(M) x 64(N), K staged 64 with cp.async double buffering.
// grid = (16, 8), 256 threads.
// ---------------------------------------------------------------------------
__global__ void step_kernel(const float* __restrict__ W,
                            int te_f, int te_b, int pin, int pout) {
    // Row stride 68 floats = 272 B = 17 * 16 B  -> 16B-aligned rows for cp.async
    __shared__ __align__(16) float Ss[2][16][68];
    __shared__ __align__(16) float Ws[2][64][68];

    const float* __restrict__ sin_ = g_s[pin];
    float*       __restrict__ sout = g_s[pout];

    const int tid = threadIdx.x;
    const int tx  = tid & 15;
    const int ty  = tid >> 4;
    const int nb  = blockIdx.x;     // 0..15
    const int mb  = blockIdx.y;     // 0..7
    const int n0  = nb * 64;
    const int m0  = mb * 16;

    // stage loader: k-stage s (16x64) + W (64x64) via cp.async
    const int s_r  = tid >> 4;      // 0..15
    const int s_c4 = tid & 15;      // 0..15

    float4 acc = {0.f, 0.f, 0.f, 0.f};

    // ---- prefetch stage 0 ----
    {
        unsigned sa = (unsigned)__cvta_generic_to_shared(&Ss[0][s_r][s_c4 * 4]);
        const float* g = &sin_[(m0 + s_r) * D_ + s_c4 * 4];
        asm volatile("cp.async.cg.shared.global [%0], [%1], 16;\n" :: "r"(sa), "l"(g));
        #pragma unroll
        for (int i = 0; i < 4; i++) {
            int idx = i * 256 + tid;
            int r = idx >> 4, c4 = idx & 15;
            unsigned wa = (unsigned)__cvta_generic_to_shared(&Ws[0][r][c4 * 4]);
            const float* gw = &W[(size_t)r * D_ + n0 + c4 * 4];
            asm volatile("cp.async.cg.shared.global [%0], [%1], 16;\n" :: "r"(wa), "l"(gw));
        }
        asm volatile("cp.async.commit_group;\n");
    }

    #pragma unroll 1
    for (int s = 0; s < 16; s++) {
        const int buf = s & 1;
        asm volatile("cp.async.wait_group 0;\n");
        __syncthreads();

        // prefetch next stage into the other buffer (overlaps compute below)
        if (s + 1 < 16) {
            const int k0n = (s + 1) << 6;
            unsigned sa = (unsigned)__cvta_generic_to_shared(&Ss[buf ^ 1][s_r][s_c4 * 4]);
            const float* g = &sin_[(m0 + s_r) * D_ + k0n + s_c4 * 4];
            asm volatile("cp.async.cg.shared.global [%0], [%1], 16;\n" :: "r"(sa), "l"(g));
            #pragma unroll
            for (int i = 0; i < 4; i++) {
                int idx = i * 256 + tid;
                int r = idx >> 4, c4 = idx & 15;
                unsigned wa = (unsigned)__cvta_generic_to_shared(&Ws[buf ^ 1][r][c4 * 4]);
                const float* gw = &W[(size_t)(k0n + r) * D_ + n0 + c4 * 4];
                asm volatile("cp.async.cg.shared.global [%0], [%1], 16;\n" :: "r"(wa), "l"(gw));
            }
            asm volatile("cp.async.commit_group;\n");
        }

        // compute 64 k's from buf
        #pragma unroll
        for (int k = 0; k < 64; k += 4) {
            float4 a = *(const float4*)&Ss[buf][ty][k];
            float4 w;
            w = *(const float4*)&Ws[buf][k + 0][tx * 4];
            acc.x += a.x * w.x; acc.y += a.x * w.y; acc.z += a.x * w.z; acc.w += a.x * w.w;
            w = *(const float4*)&Ws[buf][k + 1][tx * 4];
            acc.x += a.y * w.x; acc.y += a.y * w.y; acc.z += a.y * w.z; acc.w += a.y * w.w;
            w = *(const float4*)&Ws[buf][k + 2][tx * 4];
            acc.x += a.z * w.x; acc.y += a.z * w.y; acc.z += a.z * w.z; acc.w += a.z * w.w;
            w = *(const float4*)&Ws[buf][k + 3][tx * 4];
            acc.x += a.w * w.x; acc.y += a.w * w.y; acc.z += a.w * w.z; acc.w += a.w * w.w;
        }
    }

    // epilogue: s_next = erf(E[te] + acc/32)
    const float inv32 = 0.03125f;
    const int m  = m0 + ty;
    const int te = (m < B_) ? te_f : te_b;
    const int mm = (m < B_) ? m : (m - B_);
    const float4 e4 = *(const float4*)&g_E[((size_t)te * B_ + mm) * D_ + n0 + tx * 4];
    float4 o;
    o.x = erff(e4.x + acc.x * inv32);
    o.y = erff(e4.y + acc.y * inv32);
    o.z = erff(e4.z + acc.z * inv32);
    o.w = erff(e4.w + acc.w * inv32);
    *(float4*)&sout[m * D_ + n0 + tx * 4] = o;
}

// ---------------------------------------------------------------------------
// Output: out[b] = (sum_d sf[b][d]*v[d] + sb[b][d]*v[1024+d]) / 32
// ---------------------------------------------------------------------------
__global__ void out_kernel(const float* __restrict__ v, float* __restrict__ out,
                           int pin) {
    const float* __restrict__ sfin = g_s[pin];
    const int b   = blockIdx.x;
    const int tid = threadIdx.x;
    float sum = 0.f;
    for (int d = tid; d < D_; d += 256) {
        sum += sfin[b * D_ + d] * v[d];
        sum += sfin[(B_ + b) * D_ + d] * v[D_ + d];
    }
    __shared__ float red[256];
    red[tid] = sum;
    __syncthreads();
    #pragma unroll
    for (int s = 128; s > 0; s >>= 1) {
        if (tid < s) red[tid] += red[tid + s];
        __syncthreads();
    }
    if (tid == 0) out[b] = red[0] * 0.03125f;
}

// ---------------------------------------------------------------------------
// kernel_launch: graph-capturable (kernel launches only)
// ---------------------------------------------------------------------------
extern "C" void kernel_launch(void* const* d_in, const int* in_sizes, int n_in,
                              void* d_out, int out_size) {
    const float* inp  = (const float*)d_in[0];   // (64, 512, 256)
    const float* W    = (const float*)d_in[1];   // (1024, 1024)
    const float* U    = (const float*)d_in[2];   // (256, 1024)
    const float* bias = (const float*)d_in[3];   // (1024,)
    const float* v    = (const float*)d_in[4];   // (2048, 1)
    float* out        = (float*)d_out;           // (64, 1)

    // embed: E[t][b][d]
    embed_kernel<<<dim3(16, T_), 256>>>(inp, U, bias);

    // s_0 = erf(E_first)
    s0_kernel<<<512, 256>>>();

    // recurrence: 511 steps; step t produces s_{t+1}
    //   fwd rows use E[t+1], bwd rows use E[T-2-t]
    for (int t = 0; t < T_ - 1; t++) {
        step_kernel<<<dim3(16, 8), 256>>>(W, t + 1, T_ - 2 - t, t & 1, (t + 1) & 1);
    }

    // classifier head on s_{T-1} (buffer parity (T-1)&1 = 1)
    out_kernel<<<B_, 256>>>(v, out, (T_ - 1) & 1);
}

// round 5
// speedup vs baseline: 3.5478x; 2.4956x over previous
#include <cuda_runtime.h>
#include <cuda_bf16.h>
#include <math.h>
#include <stdint.h>

// Problem constants
#define B_   64
#define T_   512
#define I_   256
#define D_   1024
#define M_   128
#define NCTA 128
#define NTHREADS 256
#define KSPLIT 8
#define KSLICE 128
#define NTILE  64

// ---------------------------------------------------------------------------
// Device globals (allocation-free scratch)
// ---------------------------------------------------------------------------
__device__ float g_E[T_ * B_ * D_];                         // embed [t][b][d]
__device__ __align__(16) __nv_bfloat16 g_s_hi[M_ * D_];     // state hi
__device__ __align__(16) __nv_bfloat16 g_s_lo[M_ * D_];     // state lo
__device__ __align__(16) __nv_bfloat16 g_Wt_hi[D_ * D_];    // W^T hi  [n][k]
__device__ __align__(16) __nv_bfloat16 g_Wt_lo[D_ * D_];    // W^T lo  [n][k]
__device__ float g_part[KSPLIT][M_][D_];                    // split-K partials
__device__ unsigned g_bar_cnt;
__device__ volatile unsigned g_bar_gen;

// ---------------------------------------------------------------------------
// mma.sync bf16 (sm_80 baseline — compiles for compute_103)
// D[16x8] += A[16x16] * B[16x8],  A row-major, B col-major, fp32 accum
// ---------------------------------------------------------------------------
__device__ __forceinline__ void mma_bf16(float* c, const uint32_t* a, const uint32_t* b) {
    asm volatile(
        "mma.sync.aligned.m16n8k16.row.col.f32.bf16.bf16.f32 "
        "{%0,%1,%2,%3}, {%4,%5,%6,%7}, {%8,%9}, {%0,%1,%2,%3};"
        : "+f"(c[0]), "+f"(c[1]), "+f"(c[2]), "+f"(c[3])
        : "r"(a[0]), "r"(a[1]), "r"(a[2]), "r"(a[3]), "r"(b[0]), "r"(b[1]));
}

__device__ __forceinline__ void grid_barrier() {
    __threadfence();
    __syncthreads();
    if (threadIdx.x == 0) {
        unsigned old = g_bar_gen;
        unsigned t = atomicAdd(&g_bar_cnt, 1u);
        if (t == gridDim.x - 1) {
            g_bar_cnt = 0;
            __threadfence();
            g_bar_gen = old + 1;
        } else {
            while (g_bar_gen == old) { }
            __threadfence();
        }
    }
    __syncthreads();
}

// ---------------------------------------------------------------------------
// Embed: E[t][b][d] = dot(inp[b,t,:], U[:,d]) / 16 + bias[d]
// ---------------------------------------------------------------------------
__global__ void embed_kernel(const float* __restrict__ inp,
                             const float* __restrict__ U,
                             const float* __restrict__ bias) {
    __shared__ float AsT[32][68];
    __shared__ float Bs[32][68];

    const int tid = threadIdx.x;
    const int t   = blockIdx.y;
    const int nb  = blockIdx.x;
    const int tx  = tid & 15;
    const int ty  = tid >> 4;
    const int n0  = nb * 64;

    float4 acc0 = {0,0,0,0}, acc1 = {0,0,0,0}, acc2 = {0,0,0,0}, acc3 = {0,0,0,0};

    for (int k0 = 0; k0 < I_; k0 += 32) {
        __syncthreads();
        #pragma unroll
        for (int i = 0; i < 2; i++) {
            int idx = i * 256 + tid;
            int r   = idx >> 3;
            int c4  = idx & 7;
            float4 a = *(const float4*)&inp[((size_t)r * T_ + t) * I_ + k0 + c4 * 4];
            AsT[c4 * 4 + 0][r] = a.x;
            AsT[c4 * 4 + 1][r] = a.y;
            AsT[c4 * 4 + 2][r] = a.z;
            AsT[c4 * 4 + 3][r] = a.w;
        }
        #pragma unroll
        for (int i = 0; i < 2; i++) {
            int idx = i * 256 + tid;
            int r   = idx >> 4;
            int c4  = idx & 15;
            *(float4*)&Bs[r][c4 * 4] =
                *(const float4*)&U[(size_t)(k0 + r) * D_ + n0 + c4 * 4];
        }
        __syncthreads();
        #pragma unroll
        for (int k = 0; k < 32; k++) {
            float4 a = *(const float4*)&AsT[k][ty * 4];
            float4 w = *(const float4*)&Bs[k][tx * 4];
            acc0.x += a.x * w.x; acc0.y += a.x * w.y; acc0.z += a.x * w.z; acc0.w += a.x * w.w;
            acc1.x += a.y * w.x; acc1.y += a.y * w.y; acc1.z += a.y * w.z; acc1.w += a.y * w.w;
            acc2.x += a.z * w.x; acc2.y += a.z * w.y; acc2.z += a.z * w.z; acc2.w += a.z * w.w;
            acc3.x += a.w * w.x; acc3.y += a.w * w.y; acc3.z += a.w * w.z; acc3.w += a.w * w.w;
        }
    }

    const int n = n0 + tx * 4;
    float4 bv = *(const float4*)&bias[n];
    const float inv16 = 0.0625f;
    float4 o; int b;

    b = ty * 4 + 0;
    o.x = acc0.x * inv16 + bv.x; o.y = acc0.y * inv16 + bv.y;
    o.z = acc0.z * inv16 + bv.z; o.w = acc0.w * inv16 + bv.w;
    *(float4*)&g_E[(size_t)t * (B_ * D_) + b * D_ + n] = o;
    b = ty * 4 + 1;
    o.x = acc1.x * inv16 + bv.x; o.y = acc1.y * inv16 + bv.y;
    o.z = acc1.z * inv16 + bv.z; o.w = acc1.w * inv16 + bv.w;
    *(float4*)&g_E[(size_t)t * (B_ * D_) + b * D_ + n] = o;
    b = ty * 4 + 2;
    o.x = acc2.x * inv16 + bv.x; o.y = acc2.y * inv16 + bv.y;
    o.z = acc2.z * inv16 + bv.z; o.w = acc2.w * inv16 + bv.w;
    *(float4*)&g_E[(size_t)t * (B_ * D_) + b * D_ + n] = o;
    b = ty * 4 + 3;
    o.x = acc3.x * inv16 + bv.x; o.y = acc3.y * inv16 + bv.y;
    o.z = acc3.z * inv16 + bv.z; o.w = acc3.w * inv16 + bv.w;
    *(float4*)&g_E[(size_t)t * (B_ * D_) + b * D_ + n] = o;
}

// ---------------------------------------------------------------------------
// W^T split into bf16 hi/lo: Wt[n][k] = W[k][n]
// ---------------------------------------------------------------------------
__global__ void wt_split_kernel(const float* __restrict__ W) {
    const int n = blockIdx.x;
    for (int k = threadIdx.x; k < D_; k += 256) {
        float w = W[(size_t)k * D_ + n];
        __nv_bfloat16 h = __float2bfloat16(w);
        g_Wt_hi[(size_t)n * D_ + k] = h;
        g_Wt_lo[(size_t)n * D_ + k] = __float2bfloat16(w - __bfloat162float(h));
    }
}

// ---------------------------------------------------------------------------
// s_0 = erf(E_first), split into bf16 hi/lo
// ---------------------------------------------------------------------------
__global__ void s0_kernel() {
    int idx = blockIdx.x * blockDim.x + threadIdx.x;   // 131072
    int m = idx >> 10;
    int d = idx & 1023;
    float e = (m < B_) ? g_E[(size_t)0 * (B_ * D_) + m * D_ + d]
                       : g_E[(size_t)(T_ - 1) * (B_ * D_) + (m - B_) * D_ + d];
    float s = erff(e);
    __nv_bfloat16 h = __float2bfloat16(s);
    g_s_hi[idx] = h;
    g_s_lo[idx] = __float2bfloat16(s - __bfloat162float(h));
}

// ---------------------------------------------------------------------------
// Persistent recurrence kernel: 511 steps, mma.sync bf16-split GEMM + split-K.
// grid = 128 CTAs (16 N-tiles x 8 K-slices), 256 threads, 1 wave.
//
// SMEM layout (dynamic), bf16 rows of 128 elems padded to stride 68 words:
//   A_hi [128][136B-row]  34816 B     A_lo  +34816
//   B_hi [ 64][136B-row]  17408 B     B_lo  +17408
// ---------------------------------------------------------------------------
#define SROW 68                      // words per 128-bf16 row (conflict-free)
#define A_HI_W 0
#define A_LO_W (128 * SROW)
#define B_HI_W (256 * SROW)
#define B_LO_W (320 * SROW)
#define SMEM_BYTES (384 * SROW * 4)  // 104448 B

__global__ void __launch_bounds__(NTHREADS, 1) rnn_kernel() {
    extern __shared__ __align__(16) uint32_t smw[];
    const int tid = threadIdx.x;
    const int wid = tid >> 5;
    const int lt  = tid & 31;
    const int g4  = lt >> 2;       // 0..7  (fragment "groupID")
    const int q4  = lt & 3;        // 0..3
    const int bid = blockIdx.x;
    const int nb  = bid & 15;
    const int kb  = bid >> 4;
    const int n0  = nb * NTILE;
    const int k0  = kb * KSLICE;

    // warp tile: 32(M) x 32(N);  warps: 4(M) x 2(N)
    const int w_m = wid >> 1;
    const int w_n = wid & 1;
    const int m_base = w_m * 32;
    const int n_base = w_n * 32;

    // ---- Preload B = W^T slices (constant across all steps) ----
    // rows n = 0..63 of slice, 128 bf16 each (= 16 cp.async 16B chunks)
    for (int hl = 0; hl < 2; hl++) {
        const __nv_bfloat16* src = hl ? g_Wt_lo : g_Wt_hi;
        const int base_w = hl ? B_LO_W : B_HI_W;
        #pragma unroll
        for (int i = 0; i < 4; i++) {
            int idx = i * 256 + tid;          // 0..1023
            int r   = idx >> 4;               // 0..63
            int ch  = idx & 15;               // 16B chunk
            uint32_t dst = (uint32_t)__cvta_generic_to_shared(&smw[base_w + r * SROW + ch * 4]);
            const char* g = (const char*)(src + (size_t)(n0 + r) * D_ + k0) + ch * 16;
            asm volatile("cp.async.cg.shared.global [%0], [%1], 16;\n" :: "r"(dst), "l"(g));
        }
    }
    asm volatile("cp.async.commit_group;\n");
    asm volatile("cp.async.wait_group 0;\n");
    __syncthreads();

    // reduce-phase assignment: 4 consecutive elements per thread, chip-wide
    const int g_tid = bid * NTHREADS + tid;
    const int r_m   = (g_tid * 4) >> 10;
    const int r_d   = (g_tid * 4) & 1023;

    for (int t = 0; t < T_ - 1; t++) {
        // ---- Load A tiles: s_hi / s_lo slices [128 x 128 bf16] ----
        #pragma unroll
        for (int hl = 0; hl < 2; hl++) {
            const __nv_bfloat16* src = hl ? g_s_lo : g_s_hi;
            const int base_w = hl ? A_LO_W : A_HI_W;
            #pragma unroll
            for (int i = 0; i < 8; i++) {
                int idx = i * 256 + tid;      // 0..2047
                int r   = idx >> 4;           // 0..127
                int ch  = idx & 15;
                uint32_t dst = (uint32_t)__cvta_generic_to_shared(&smw[base_w + r * SROW + ch * 4]);
                const char* g = (const char*)(src + (size_t)r * D_ + k0) + ch * 16;
                asm volatile("cp.async.cg.shared.global [%0], [%1], 16;\n" :: "r"(dst), "l"(g));
            }
        }
        asm volatile("cp.async.commit_group;\n");
        asm volatile("cp.async.wait_group 0;\n");
        __syncthreads();

        // ---- GEMM: C[32x32 per warp] = A_hi*B_hi + A_hi*B_lo + A_lo*B_hi ----
        float acc[2][4][4];
        #pragma unroll
        for (int mt = 0; mt < 2; mt++)
            #pragma unroll
            for (int nt = 0; nt < 4; nt++)
                #pragma unroll
                for (int j = 0; j < 4; j++) acc[mt][nt][j] = 0.f;

        #pragma unroll 2
        for (int kc = 0; kc < 8; kc++) {
            const int kw = kc * 8;           // word offset of k-chunk
            // A fragments (hi & lo): 2 m-tiles
            uint32_t a_hi[2][4], a_lo[2][4];
            #pragma unroll
            for (int mt = 0; mt < 2; mt++) {
                const int r0 = (m_base + mt * 16 + g4) * SROW + kw + q4;
                const int r1 = r0 + 8 * SROW;
                a_hi[mt][0] = smw[A_HI_W + r0];
                a_hi[mt][1] = smw[A_HI_W + r1];
                a_hi[mt][2] = smw[A_HI_W + r0 + 4];
                a_hi[mt][3] = smw[A_HI_W + r1 + 4];
                a_lo[mt][0] = smw[A_LO_W + r0];
                a_lo[mt][1] = smw[A_LO_W + r1];
                a_lo[mt][2] = smw[A_LO_W + r0 + 4];
                a_lo[mt][3] = smw[A_LO_W + r1 + 4];
            }
            // B fragments (hi & lo): 4 n-tiles
            uint32_t b_hi[4][2], b_lo[4][2];
            #pragma unroll
            for (int nt = 0; nt < 4; nt++) {
                const int nw = (n_base + nt * 8 + g4) * SROW + kw + q4;
                b_hi[nt][0] = smw[B_HI_W + nw];
                b_hi[nt][1] = smw[B_HI_W + nw + 4];
                b_lo[nt][0] = smw[B_LO_W + nw];
                b_lo[nt][1] = smw[B_LO_W + nw + 4];
            }
            #pragma unroll
            for (int mt = 0; mt < 2; mt++)
                #pragma unroll
                for (int nt = 0; nt < 4; nt++) {
                    mma_bf16(acc[mt][nt], a_hi[mt], b_hi[nt]);
                    mma_bf16(acc[mt][nt], a_hi[mt], b_lo[nt]);
                    mma_bf16(acc[mt][nt], a_lo[mt], b_hi[nt]);
                }
        }

        // ---- Write split-K partials ----
        #pragma unroll
        for (int mt = 0; mt < 2; mt++) {
            const int R = m_base + mt * 16 + g4;
            #pragma unroll
            for (int nt = 0; nt < 4; nt++) {
                const int C = n0 + n_base + nt * 8 + q4 * 2;
                *(float2*)&g_part[kb][R][C]     = make_float2(acc[mt][nt][0], acc[mt][nt][1]);
                *(float2*)&g_part[kb][R + 8][C] = make_float2(acc[mt][nt][2], acc[mt][nt][3]);
            }
        }

        grid_barrier();

        // ---- Reduce: sum 8 partials, c = sum/32, s = erf(E + c), split ----
        {
            float4 sum = {0.f, 0.f, 0.f, 0.f};
            #pragma unroll
            for (int kk = 0; kk < KSPLIT; kk++) {
                float4 p = *(const float4*)&g_part[kk][r_m][r_d];
                sum.x += p.x; sum.y += p.y; sum.z += p.z; sum.w += p.w;
            }
            const float inv32 = 0.03125f;
            int te, mm;
            if (r_m < B_) { te = t + 1;       mm = r_m; }
            else          { te = T_ - 2 - t;  mm = r_m - B_; }
            const float4 e4 = *(const float4*)&g_E[((size_t)te * B_ + mm) * D_ + r_d];
            float s0 = erff(e4.x + sum.x * inv32);
            float s1 = erff(e4.y + sum.y * inv32);
            float s2 = erff(e4.z + sum.z * inv32);
            float s3 = erff(e4.w + sum.w * inv32);

            __nv_bfloat16 h0 = __float2bfloat16(s0);
            __nv_bfloat16 h1 = __float2bfloat16(s1);
            __nv_bfloat16 h2 = __float2bfloat16(s2);
            __nv_bfloat16 h3 = __float2bfloat16(s3);
            __nv_bfloat16 l0 = __float2bfloat16(s0 - __bfloat162float(h0));
            __nv_bfloat16 l1 = __float2bfloat16(s1 - __bfloat162float(h1));
            __nv_bfloat16 l2 = __float2bfloat16(s2 - __bfloat162float(h2));
            __nv_bfloat16 l3 = __float2bfloat16(s3 - __bfloat162float(h3));

            uint2 ph, pl;
            ph.x = ((uint32_t)__bfloat16_as_ushort(h1) << 16) | __bfloat16_as_ushort(h0);
            ph.y = ((uint32_t)__bfloat16_as_ushort(h3) << 16) | __bfloat16_as_ushort(h2);
            pl.x = ((uint32_t)__bfloat16_as_ushort(l1) << 16) | __bfloat16_as_ushort(l0);
            pl.y = ((uint32_t)__bfloat16_as_ushort(l3) << 16) | __bfloat16_as_ushort(l2);
            *(uint2*)&g_s_hi[(size_t)r_m * D_ + r_d] = ph;
            *(uint2*)&g_s_lo[(size_t)r_m * D_ + r_d] = pl;
        }

        grid_barrier();
    }
}

// ---------------------------------------------------------------------------
// Output head: out[b] = (sum_d sf[b][d]*v[d] + sb[b][d]*v[1024+d]) / 32
// ---------------------------------------------------------------------------
__global__ void out_kernel(const float* __restrict__ v, float* __restrict__ out) {
    const int b   = blockIdx.x;
    const int tid = threadIdx.x;
    float sum = 0.f;
    for (int d = tid; d < D_; d += 256) {
        float sf = __bfloat162float(g_s_hi[b * D_ + d]) + __bfloat162float(g_s_lo[b * D_ + d]);
        float sb = __bfloat162float(g_s_hi[(B_ + b) * D_ + d]) + __bfloat162float(g_s_lo[(B_ + b) * D_ + d]);
        sum += sf * v[d] + sb * v[D_ + d];
    }
    __shared__ float red[256];
    red[tid] = sum;
    __syncthreads();
    #pragma unroll
    for (int s = 128; s > 0; s >>= 1) {
        if (tid < s) red[tid] += red[tid + s];
        __syncthreads();
    }
    if (tid == 0) out[b] = red[0] * 0.03125f;
}

// ---------------------------------------------------------------------------
// kernel_launch: graph-capturable (kernel launches only)
// ---------------------------------------------------------------------------
extern "C" void kernel_launch(void* const* d_in, const int* in_sizes, int n_in,
                              void* d_out, int out_size) {
    const float* inp  = (const float*)d_in[0];   // (64, 512, 256)
    const float* W    = (const float*)d_in[1];   // (1024, 1024)
    const float* U    = (const float*)d_in[2];   // (256, 1024)
    const float* bias = (const float*)d_in[3];   // (1024,)
    const float* v    = (const float*)d_in[4];   // (2048, 1)
    float* out        = (float*)d_out;           // (64, 1)

    static bool attr_set = false;
    if (!attr_set) {
        cudaFuncSetAttribute(rnn_kernel, cudaFuncAttributeMaxDynamicSharedMemorySize, SMEM_BYTES);
        attr_set = true;
    }

    embed_kernel<<<dim3(16, T_), 256>>>(inp, U, bias);
    wt_split_kernel<<<D_, 256>>>(W);
    s0_kernel<<<512, 256>>>();
    rnn_kernel<<<NCTA, NTHREADS, SMEM_BYTES>>>();
    out_kernel<<<B_, 256>>>(v, out);
}

// round 6
// speedup vs baseline: 4.5976x; 1.2959x over previous
#include <cuda_runtime.h>
#include <cuda_bf16.h>
#include <math.h>
#include <stdint.h>

// Problem constants
#define B_   64
#define T_   512
#define I_   256
#define D_   1024
#define M_   128
#define NCTA 128
#define NTHREADS 256
#define KSPLIT 8
#define KSLICE 128
#define NTILE  64

// ---------------------------------------------------------------------------
// Device globals (allocation-free scratch)
// ---------------------------------------------------------------------------
__device__ float g_E[T_ * B_ * D_];                          // embed [t][b][d]
__device__ __align__(16) __nv_bfloat16 g_s_hi[M_ * D_];
__device__ __align__(16) __nv_bfloat16 g_s_lo[M_ * D_];
__device__ __align__(16) __nv_bfloat16 g_Wt_hi[D_ * D_];     // W^T [n][k]
__device__ __align__(16) __nv_bfloat16 g_Wt_lo[D_ * D_];
__device__ __align__(16) __nv_bfloat16 g_in_hi[B_ * T_ * I_]; // inp split
__device__ __align__(16) __nv_bfloat16 g_in_lo[B_ * T_ * I_];
__device__ __align__(16) __nv_bfloat16 g_Ut_hi[D_ * I_];     // U^T [d][i]
__device__ __align__(16) __nv_bfloat16 g_Ut_lo[D_ * I_];
__device__ float g_part[KSPLIT][M_][D_];                     // split-K partials
__device__ unsigned g_bar;                                   // monotonic barrier

// ---------------------------------------------------------------------------
// mma.sync bf16 + ldmatrix (sm_80 baseline — compiles for compute_103)
// ---------------------------------------------------------------------------
__device__ __forceinline__ void mma_bf16(float* c, const uint32_t* a, const uint32_t* b) {
    asm volatile(
        "mma.sync.aligned.m16n8k16.row.col.f32.bf16.bf16.f32 "
        "{%0,%1,%2,%3}, {%4,%5,%6,%7}, {%8,%9}, {%0,%1,%2,%3};"
        : "+f"(c[0]), "+f"(c[1]), "+f"(c[2]), "+f"(c[3])
        : "r"(a[0]), "r"(a[1]), "r"(a[2]), "r"(a[3]), "r"(b[0]), "r"(b[1]));
}

__device__ __forceinline__ void ldm_x4(uint32_t* r, uint32_t saddr) {
    asm volatile(
        "ldmatrix.sync.aligned.m8n8.x4.shared.b16 {%0,%1,%2,%3}, [%4];"
        : "=r"(r[0]), "=r"(r[1]), "=r"(r[2]), "=r"(r[3]) : "r"(saddr));
}

// ---------------------------------------------------------------------------
// Grid barrier: monotonic counter, release-red arrive + acquire spin by t0,
// one threadfence (L1 invalidate) after release from the spin.
// ---------------------------------------------------------------------------
__device__ __forceinline__ void grid_barrier(unsigned target) {
    __syncthreads();
    if (threadIdx.x == 0) {
        asm volatile("red.release.gpu.global.add.u32 [%0], 1;"
                     :: "l"(&g_bar) : "memory");
        unsigned v;
        do {
            asm volatile("ld.acquire.gpu.global.u32 %0, [%1];"
                         : "=r"(v) : "l"(&g_bar) : "memory");
        } while (v < target);
        __threadfence();   // CCTL.IVALL: invalidate L1 so partial LDGs are fresh
    }
    __syncthreads();
}

__global__ void zero_bar_kernel() { if (threadIdx.x == 0) g_bar = 0; }

// ---------------------------------------------------------------------------
// Split kernels (one-time prep per launch)
// ---------------------------------------------------------------------------
__global__ void inp_split_kernel(const float* __restrict__ inp) {
    int idx = blockIdx.x * blockDim.x + threadIdx.x;    // float4 index
    const int N4 = B_ * T_ * I_ / 4;
    if (idx >= N4) return;
    float4 a = ((const float4*)inp)[idx];
    __nv_bfloat16 h0 = __float2bfloat16(a.x), h1 = __float2bfloat16(a.y);
    __nv_bfloat16 h2 = __float2bfloat16(a.z), h3 = __float2bfloat16(a.w);
    __nv_bfloat16 l0 = __float2bfloat16(a.x - __bfloat162float(h0));
    __nv_bfloat16 l1 = __float2bfloat16(a.y - __bfloat162float(h1));
    __nv_bfloat16 l2 = __float2bfloat16(a.z - __bfloat162float(h2));
    __nv_bfloat16 l3 = __float2bfloat16(a.w - __bfloat162float(h3));
    uint2 ph, pl;
    ph.x = ((uint32_t)__bfloat16_as_ushort(h1) << 16) | __bfloat16_as_ushort(h0);
    ph.y = ((uint32_t)__bfloat16_as_ushort(h3) << 16) | __bfloat16_as_ushort(h2);
    pl.x = ((uint32_t)__bfloat16_as_ushort(l1) << 16) | __bfloat16_as_ushort(l0);
    pl.y = ((uint32_t)__bfloat16_as_ushort(l3) << 16) | __bfloat16_as_ushort(l2);
    *(uint2*)&g_in_hi[idx * 4] = ph;
    *(uint2*)&g_in_lo[idx * 4] = pl;
}

__global__ void ut_split_kernel(const float* __restrict__ U) {
    const int d = blockIdx.x;
    for (int i = threadIdx.x; i < I_; i += 256) {
        float u = U[(size_t)i * D_ + d];
        __nv_bfloat16 h = __float2bfloat16(u);
        g_Ut_hi[(size_t)d * I_ + i] = h;
        g_Ut_lo[(size_t)d * I_ + i] = __float2bfloat16(u - __bfloat162float(h));
    }
}

__global__ void wt_split_kernel(const float* __restrict__ W) {
    const int n = blockIdx.x;
    for (int k = threadIdx.x; k < D_; k += 256) {
        float w = W[(size_t)k * D_ + n];
        __nv_bfloat16 h = __float2bfloat16(w);
        g_Wt_hi[(size_t)n * D_ + k] = h;
        g_Wt_lo[(size_t)n * D_ + k] = __float2bfloat16(w - __bfloat162float(h));
    }
}

// ---------------------------------------------------------------------------
// SMEM layout (shared by embed_mma and rnn kernels):
// bf16 rows of 128 elems, stride 68 words (conflict-free for LDS & ldmatrix)
// ---------------------------------------------------------------------------
#define SROW 68
#define A_HI_W 0
#define A_LO_W (128 * SROW)
#define B_HI_W (256 * SROW)
#define B_LO_W (320 * SROW)
#define SMEM_BYTES (384 * SROW * 4)   // 104448 B

// ---------------------------------------------------------------------------
// Embed (tensor core): E[t][b][:] = inp[b,t,:] @ U / 16 + bias
// A = inp rows (b*512+t), B = U^T [d][i]; K=256 in 2 chunks of 128.
// grid = (16 ntile, 256 mtile), 256 threads. mtile -> b = mtile>>2, t0=(mtile&3)*128
// ---------------------------------------------------------------------------
__global__ void __launch_bounds__(NTHREADS, 1) embed_mma_kernel(
        const float* __restrict__ bias) {
    extern __shared__ __align__(16) uint32_t smw[];
    const int tid = threadIdx.x;
    const int wid = tid >> 5;
    const int lt  = tid & 31;
    const int g4  = lt >> 2;
    const int q4  = lt & 3;
    const int nb  = blockIdx.x;
    const int mt_idx = blockIdx.y;
    const int n0  = nb * NTILE;
    const int b   = mt_idx >> 2;
    const int t0  = (mt_idx & 3) << 7;
    const size_t row0 = (size_t)b * T_ + t0;     // first inp row

    const int w_m = wid >> 1;
    const int w_n = wid & 1;
    const int m_base = w_m * 32;
    const int n_base = w_n * 32;

    // ldmatrix lane addressing (word offsets relative to tile base)
    const int a_r  = lt & 15;                 // A row within 16
    const int a_cw = ((lt >> 4) & 1) * 4;     // A col word
    const int b_r  = ((lt >> 4) & 1) * 8 + (lt & 7);
    const int b_cw = ((lt >> 3) & 1) * 4;

    uint32_t smem_b32 = (uint32_t)__cvta_generic_to_shared(smw);

    float acc[2][4][4];
    #pragma unroll
    for (int mt = 0; mt < 2; mt++)
        #pragma unroll
        for (int nt = 0; nt < 4; nt++)
            #pragma unroll
            for (int j = 0; j < 4; j++) acc[mt][nt][j] = 0.f;

    for (int chunk = 0; chunk < 2; chunk++) {
        const int i0 = chunk * 128;
        __syncthreads();
        // A: 128 rows x 128 i (hi & lo)
        #pragma unroll
        for (int hl = 0; hl < 2; hl++) {
            const __nv_bfloat16* src = hl ? g_in_lo : g_in_hi;
            const int base_w = hl ? A_LO_W : A_HI_W;
            #pragma unroll
            for (int i = 0; i < 8; i++) {
                int idx = i * 256 + tid;
                int r   = idx >> 4;
                int ch  = idx & 15;
                uint32_t dst = smem_b32 + (base_w + r * SROW + ch * 4) * 4;
                const char* g = (const char*)(src + (row0 + r) * I_ + i0) + ch * 16;
                asm volatile("cp.async.cg.shared.global [%0], [%1], 16;\n" :: "r"(dst), "l"(g));
            }
        }
        // B: 64 rows (n) x 128 i
        #pragma unroll
        for (int hl = 0; hl < 2; hl++) {
            const __nv_bfloat16* src = hl ? g_Ut_lo : g_Ut_hi;
            const int base_w = hl ? B_LO_W : B_HI_W;
            #pragma unroll
            for (int i = 0; i < 4; i++) {
                int idx = i * 256 + tid;
                int r   = idx >> 4;
                int ch  = idx & 15;
                uint32_t dst = smem_b32 + (base_w + r * SROW + ch * 4) * 4;
                const char* g = (const char*)(src + (size_t)(n0 + r) * I_ + i0) + ch * 16;
                asm volatile("cp.async.cg.shared.global [%0], [%1], 16;\n" :: "r"(dst), "l"(g));
            }
        }
        asm volatile("cp.async.commit_group;\n");
        asm volatile("cp.async.wait_group 0;\n");
        __syncthreads();

        #pragma unroll 2
        for (int kc = 0; kc < 8; kc++) {
            const int kw = kc * 8;
            uint32_t a_hi[2][4], a_lo[2][4], b_hi[2][4], b_lo[2][4];
            #pragma unroll
            for (int mt = 0; mt < 2; mt++) {
                int row = m_base + mt * 16 + a_r;
                ldm_x4(a_hi[mt], smem_b32 + (A_HI_W + row * SROW + kw + a_cw) * 4);
                ldm_x4(a_lo[mt], smem_b32 + (A_LO_W + row * SROW + kw + a_cw) * 4);
            }
            #pragma unroll
            for (int np = 0; np < 2; np++) {
                int row = n_base + np * 16 + b_r;
                ldm_x4(b_hi[np], smem_b32 + (B_HI_W + row * SROW + kw + b_cw) * 4);
                ldm_x4(b_lo[np], smem_b32 + (B_LO_W + row * SROW + kw + b_cw) * 4);
            }
            #pragma unroll
            for (int mt = 0; mt < 2; mt++)
                #pragma unroll
                for (int np = 0; np < 2; np++)
                    #pragma unroll
                    for (int h = 0; h < 2; h++) {
                        mma_bf16(acc[mt][np * 2 + h], a_hi[mt], &b_hi[np][h * 2]);
                        mma_bf16(acc[mt][np * 2 + h], a_hi[mt], &b_lo[np][h * 2]);
                        mma_bf16(acc[mt][np * 2 + h], a_lo[mt], &b_hi[np][h * 2]);
                    }
        }
    }

    // Epilogue: E[t][b][n] = acc/16 + bias
    const float inv16 = 0.0625f;
    #pragma unroll
    for (int nt = 0; nt < 4; nt++) {
        const int C = n0 + n_base + nt * 8 + q4 * 2;
        float2 bv = *(const float2*)&bias[C];
        #pragma unroll
        for (int mt = 0; mt < 2; mt++) {
            const int R = m_base + mt * 16 + g4;
            float2 o0 = make_float2(acc[mt][nt][0] * inv16 + bv.x,
                                    acc[mt][nt][1] * inv16 + bv.y);
            float2 o1 = make_float2(acc[mt][nt][2] * inv16 + bv.x,
                                    acc[mt][nt][3] * inv16 + bv.y);
            *(float2*)&g_E[((size_t)(t0 + R) * B_ + b) * D_ + C]     = o0;
            *(float2*)&g_E[((size_t)(t0 + R + 8) * B_ + b) * D_ + C] = o1;
        }
    }
}

// ---------------------------------------------------------------------------
// s_0 = erf(E_first), split into bf16 hi/lo
// ---------------------------------------------------------------------------
__global__ void s0_kernel() {
    int idx = blockIdx.x * blockDim.x + threadIdx.x;
    int m = idx >> 10;
    int d = idx & 1023;
    float e = (m < B_) ? g_E[(size_t)0 * (B_ * D_) + m * D_ + d]
                       : g_E[(size_t)(T_ - 1) * (B_ * D_) + (m - B_) * D_ + d];
    float s = erff(e);
    __nv_bfloat16 h = __float2bfloat16(s);
    g_s_hi[idx] = h;
    g_s_lo[idx] = __float2bfloat16(s - __bfloat162float(h));
}

// ---------------------------------------------------------------------------
// Persistent recurrence kernel: 511 steps
// ---------------------------------------------------------------------------
__global__ void __launch_bounds__(NTHREADS, 1) rnn_kernel() {
    extern __shared__ __align__(16) uint32_t smw[];
    const int tid = threadIdx.x;
    const int wid = tid >> 5;
    const int lt  = tid & 31;
    const int g4  = lt >> 2;
    const int q4  = lt & 3;
    const int bid = blockIdx.x;
    const int nb  = bid & 15;
    const int kb  = bid >> 4;
    const int n0  = nb * NTILE;
    const int k0  = kb * KSLICE;

    const int w_m = wid >> 1;
    const int w_n = wid & 1;
    const int m_base = w_m * 32;
    const int n_base = w_n * 32;

    const int a_r  = lt & 15;
    const int a_cw = ((lt >> 4) & 1) * 4;
    const int b_r  = ((lt >> 4) & 1) * 8 + (lt & 7);
    const int b_cw = ((lt >> 3) & 1) * 4;

    uint32_t smem_b32 = (uint32_t)__cvta_generic_to_shared(smw);

    // ---- Preload B = W^T slices (constant across all steps) ----
    #pragma unroll
    for (int hl = 0; hl < 2; hl++) {
        const __nv_bfloat16* src = hl ? g_Wt_lo : g_Wt_hi;
        const int base_w = hl ? B_LO_W : B_HI_W;
        #pragma unroll
        for (int i = 0; i < 4; i++) {
            int idx = i * 256 + tid;
            int r   = idx >> 4;
            int ch  = idx & 15;
            uint32_t dst = smem_b32 + (base_w + r * SROW + ch * 4) * 4;
            const char* g = (const char*)(src + (size_t)(n0 + r) * D_ + k0) + ch * 16;
            asm volatile("cp.async.cg.shared.global [%0], [%1], 16;\n" :: "r"(dst), "l"(g));
        }
    }
    asm volatile("cp.async.commit_group;\n");
    asm volatile("cp.async.wait_group 0;\n");
    __syncthreads();

    // precomputed ldmatrix byte addresses (k advances by 32B per kc)
    uint32_t aaddr_hi[2], aaddr_lo[2], baddr_hi[2], baddr_lo[2];
    #pragma unroll
    for (int mt = 0; mt < 2; mt++) {
        int row = m_base + mt * 16 + a_r;
        aaddr_hi[mt] = smem_b32 + (A_HI_W + row * SROW + a_cw) * 4;
        aaddr_lo[mt] = smem_b32 + (A_LO_W + row * SROW + a_cw) * 4;
    }
    #pragma unroll
    for (int np = 0; np < 2; np++) {
        int row = n_base + np * 16 + b_r;
        baddr_hi[np] = smem_b32 + (B_HI_W + row * SROW + b_cw) * 4;
        baddr_lo[np] = smem_b32 + (B_LO_W + row * SROW + b_cw) * 4;
    }

    // reduce-phase assignment: 4 consecutive elements per thread, chip-wide
    const int g_tid = bid * NTHREADS + tid;
    const int r_m   = (g_tid * 4) >> 10;
    const int r_d   = (g_tid * 4) & 1023;
    const int r_mm  = (r_m < B_) ? r_m : (r_m - B_);
    const bool r_fwd = (r_m < B_);

    for (int t = 0; t < T_ - 1; t++) {
        // ---- Load A tiles: s_hi / s_lo slices [128 x 128 bf16] ----
        #pragma unroll
        for (int hl = 0; hl < 2; hl++) {
            const __nv_bfloat16* src = hl ? g_s_lo : g_s_hi;
            const int base_w = hl ? A_LO_W : A_HI_W;
            #pragma unroll
            for (int i = 0; i < 8; i++) {
                int idx = i * 256 + tid;
                int r   = idx >> 4;
                int ch  = idx & 15;
                uint32_t dst = smem_b32 + (base_w + r * SROW + ch * 4) * 4;
                const char* g = (const char*)(src + (size_t)r * D_ + k0) + ch * 16;
                asm volatile("cp.async.cg.shared.global [%0], [%1], 16;\n" :: "r"(dst), "l"(g));
            }
        }
        asm volatile("cp.async.commit_group;\n");

        // ---- Prefetch E for this step's reduce (constant data, L1 OK) ----
        const int te = r_fwd ? (t + 1) : (T_ - 2 - t);
        const float4 e4 = *(const float4*)&g_E[((size_t)te * B_ + r_mm) * D_ + r_d];

        asm volatile("cp.async.wait_group 0;\n");
        __syncthreads();

        // ---- GEMM: C[32x32/warp] = A_hi*B_hi + A_hi*B_lo + A_lo*B_hi ----
        float acc[2][4][4];
        #pragma unroll
        for (int mt = 0; mt < 2; mt++)
            #pragma unroll
            for (int nt = 0; nt < 4; nt++)
                #pragma unroll
                for (int j = 0; j < 4; j++) acc[mt][nt][j] = 0.f;

        #pragma unroll 2
        for (int kc = 0; kc < 8; kc++) {
            const uint32_t koff = kc * 32;    // 8 words = 32 bytes
            uint32_t a_hi[2][4], a_lo[2][4], b_hi[2][4], b_lo[2][4];
            #pragma unroll
            for (int mt = 0; mt < 2; mt++) {
                ldm_x4(a_hi[mt], aaddr_hi[mt] + koff);
                ldm_x4(a_lo[mt], aaddr_lo[mt] + koff);
            }
            #pragma unroll
            for (int np = 0; np < 2; np++) {
                ldm_x4(b_hi[np], baddr_hi[np] + koff);
                ldm_x4(b_lo[np], baddr_lo[np] + koff);
            }
            #pragma unroll
            for (int mt = 0; mt < 2; mt++)
                #pragma unroll
                for (int np = 0; np < 2; np++)
                    #pragma unroll
                    for (int h = 0; h < 2; h++) {
                        mma_bf16(acc[mt][np * 2 + h], a_hi[mt], &b_hi[np][h * 2]);
                        mma_bf16(acc[mt][np * 2 + h], a_hi[mt], &b_lo[np][h * 2]);
                        mma_bf16(acc[mt][np * 2 + h], a_lo[mt], &b_hi[np][h * 2]);
                    }
        }

        // ---- Write split-K partials ----
        #pragma unroll
        for (int mt = 0; mt < 2; mt++) {
            const int R = m_base + mt * 16 + g4;
            #pragma unroll
            for (int nt = 0; nt < 4; nt++) {
                const int C = n0 + n_base + nt * 8 + q4 * 2;
                *(float2*)&g_part[kb][R][C]     = make_float2(acc[mt][nt][0], acc[mt][nt][1]);
                *(float2*)&g_part[kb][R + 8][C] = make_float2(acc[mt][nt][2], acc[mt][nt][3]);
            }
        }

        grid_barrier((2 * t + 1) * NCTA);

        // ---- Reduce: sum 8 partials, c = sum/32, s = erf(E + c), split ----
        {
            float4 sum = {0.f, 0.f, 0.f, 0.f};
            #pragma unroll
            for (int kk = 0; kk < KSPLIT; kk++) {
                float4 p = *(const float4*)&g_part[kk][r_m][r_d];
                sum.x += p.x; sum.y += p.y; sum.z += p.z; sum.w += p.w;
            }
            const float inv32 = 0.03125f;
            float s0 = erff(e4.x + sum.x * inv32);
            float s1 = erff(e4.y + sum.y * inv32);
            float s2 = erff(e4.z + sum.z * inv32);
            float s3 = erff(e4.w + sum.w * inv32);

            __nv_bfloat16 h0 = __float2bfloat16(s0);
            __nv_bfloat16 h1 = __float2bfloat16(s1);
            __nv_bfloat16 h2 = __float2bfloat16(s2);
            __nv_bfloat16 h3 = __float2bfloat16(s3);
            __nv_bfloat16 l0 = __float2bfloat16(s0 - __bfloat162float(h0));
            __nv_bfloat16 l1 = __float2bfloat16(s1 - __bfloat162float(h1));
            __nv_bfloat16 l2 = __float2bfloat16(s2 - __bfloat162float(h2));
            __nv_bfloat16 l3 = __float2bfloat16(s3 - __bfloat162float(h3));

            uint2 ph, pl;
            ph.x = ((uint32_t)__bfloat16_as_ushort(h1) << 16) | __bfloat16_as_ushort(h0);
            ph.y = ((uint32_t)__bfloat16_as_ushort(h3) << 16) | __bfloat16_as_ushort(h2);
            pl.x = ((uint32_t)__bfloat16_as_ushort(l1) << 16) | __bfloat16_as_ushort(l0);
            pl.y = ((uint32_t)__bfloat16_as_ushort(l3) << 16) | __bfloat16_as_ushort(l2);
            *(uint2*)&g_s_hi[(size_t)r_m * D_ + r_d] = ph;
            *(uint2*)&g_s_lo[(size_t)r_m * D_ + r_d] = pl;
        }

        grid_barrier((2 * t + 2) * NCTA);
    }
}

// ---------------------------------------------------------------------------
// Output head
// ---------------------------------------------------------------------------
__global__ void out_kernel(const float* __restrict__ v, float* __restrict__ out) {
    const int b   = blockIdx.x;
    const int tid = threadIdx.x;
    float sum = 0.f;
    for (int d = tid; d < D_; d += 256) {
        float sf = __bfloat162float(g_s_hi[b * D_ + d]) + __bfloat162float(g_s_lo[b * D_ + d]);
        float sb = __bfloat162float(g_s_hi[(B_ + b) * D_ + d]) + __bfloat162float(g_s_lo[(B_ + b) * D_ + d]);
        sum += sf * v[d] + sb * v[D_ + d];
    }
    __shared__ float red[256];
    red[tid] = sum;
    __syncthreads();
    #pragma unroll
    for (int s = 128; s > 0; s >>= 1) {
        if (tid < s) red[tid] += red[tid + s];
        __syncthreads();
    }
    if (tid == 0) out[b] = red[0] * 0.03125f;
}

// ---------------------------------------------------------------------------
// kernel_launch: graph-capturable (kernel launches only)
// ---------------------------------------------------------------------------
extern "C" void kernel_launch(void* const* d_in, const int* in_sizes, int n_in,
                              void* d_out, int out_size) {
    const float* inp  = (const float*)d_in[0];
    const float* W    = (const float*)d_in[1];
    const float* U    = (const float*)d_in[2];
    const float* bias = (const float*)d_in[3];
    const float* v    = (const float*)d_in[4];
    float* out        = (float*)d_out;

    static bool attr_set = false;
    if (!attr_set) {
        cudaFuncSetAttribute(rnn_kernel, cudaFuncAttributeMaxDynamicSharedMemorySize, SMEM_BYTES);
        cudaFuncSetAttribute(embed_mma_kernel, cudaFuncAttributeMaxDynamicSharedMemorySize, SMEM_BYTES);
        attr_set = true;
    }

    zero_bar_kernel<<<1, 32>>>();
    inp_split_kernel<<<(B_ * T_ * I_ / 4 + 255) / 256, 256>>>(inp);
    ut_split_kernel<<<D_, 256>>>(U);
    wt_split_kernel<<<D_, 256>>>(W);
    embed_mma_kernel<<<dim3(16, 256), NTHREADS, SMEM_BYTES>>>(bias);
    s0_kernel<<<512, 256>>>();
    rnn_kernel<<<NCTA, NTHREADS, SMEM_BYTES>>>();
    out_kernel<<<B_, 256>>>(v, out);
}

// round 7
// speedup vs baseline: 5.2749x; 1.1473x over previous
#include <cuda_runtime.h>
#include <cuda_bf16.h>
#include <math.h>
#include <stdint.h>

// Problem constants
#define B_   64
#define T_   512
#define I_   256
#define D_   1024
#define M_   128
#define NCTA 128
#define NTHREADS 256
#define KSPLIT 8
#define KSLICE 128
#define NTILE  64

// ---------------------------------------------------------------------------
// Device globals (allocation-free scratch)
// ---------------------------------------------------------------------------
__device__ float g_E[T_ * B_ * D_];                          // embed [t][b][d]
__device__ __align__(16) __nv_bfloat16 g_s_hi[M_ * D_];
__device__ __align__(16) __nv_bfloat16 g_s_lo[M_ * D_];
__device__ __align__(16) __nv_bfloat16 g_Wt_hi[D_ * D_];     // W^T [n][k]
__device__ __align__(16) __nv_bfloat16 g_Wt_lo[D_ * D_];
__device__ __align__(16) __nv_bfloat16 g_in_hi[B_ * T_ * I_]; // inp split
__device__ __align__(16) __nv_bfloat16 g_in_lo[B_ * T_ * I_];
__device__ __align__(16) __nv_bfloat16 g_Ut_hi[D_ * I_];     // U^T [d][i]
__device__ __align__(16) __nv_bfloat16 g_Ut_lo[D_ * I_];
__device__ float g_part[KSPLIT][M_][D_];                     // split-K partials
// Group barrier counters: 8 groups, each counter on its own 128B line
__device__ unsigned g_c1[8 * 32];
__device__ unsigned g_c2[8 * 32];

// ---------------------------------------------------------------------------
// mma.sync bf16 + ldmatrix (sm_80 baseline — compiles for compute_103)
// ---------------------------------------------------------------------------
__device__ __forceinline__ void mma_bf16(float* c, const uint32_t* a, const uint32_t* b) {
    asm volatile(
        "mma.sync.aligned.m16n8k16.row.col.f32.bf16.bf16.f32 "
        "{%0,%1,%2,%3}, {%4,%5,%6,%7}, {%8,%9}, {%0,%1,%2,%3};"
        : "+f"(c[0]), "+f"(c[1]), "+f"(c[2]), "+f"(c[3])
        : "r"(a[0]), "r"(a[1]), "r"(a[2]), "r"(a[3]), "r"(b[0]), "r"(b[1]));
}

__device__ __forceinline__ void ldm_x4(uint32_t* r, uint32_t saddr) {
    asm volatile(
        "ldmatrix.sync.aligned.m8n8.x4.shared.b16 {%0,%1,%2,%3}, [%4];"
        : "=r"(r[0]), "=r"(r[1]), "=r"(r[2]), "=r"(r[3]) : "r"(saddr));
}

__global__ void zero_bar_kernel() {
    int i = threadIdx.x;
    if (i < 8 * 32) { g_c1[i] = 0; g_c2[i] = 0; }
}

// ---------------------------------------------------------------------------
// Split kernels (one-time prep per launch)
// ---------------------------------------------------------------------------
__global__ void inp_split_kernel(const float* __restrict__ inp) {
    int idx = blockIdx.x * blockDim.x + threadIdx.x;    // float4 index
    const int N4 = B_ * T_ * I_ / 4;
    if (idx >= N4) return;
    float4 a = ((const float4*)inp)[idx];
    __nv_bfloat16 h0 = __float2bfloat16(a.x), h1 = __float2bfloat16(a.y);
    __nv_bfloat16 h2 = __float2bfloat16(a.z), h3 = __float2bfloat16(a.w);
    __nv_bfloat16 l0 = __float2bfloat16(a.x - __bfloat162float(h0));
    __nv_bfloat16 l1 = __float2bfloat16(a.y - __bfloat162float(h1));
    __nv_bfloat16 l2 = __float2bfloat16(a.z - __bfloat162float(h2));
    __nv_bfloat16 l3 = __float2bfloat16(a.w - __bfloat162float(h3));
    uint2 ph, pl;
    ph.x = ((uint32_t)__bfloat16_as_ushort(h1) << 16) | __bfloat16_as_ushort(h0);
    ph.y = ((uint32_t)__bfloat16_as_ushort(h3) << 16) | __bfloat16_as_ushort(h2);
    pl.x = ((uint32_t)__bfloat16_as_ushort(l1) << 16) | __bfloat16_as_ushort(l0);
    pl.y = ((uint32_t)__bfloat16_as_ushort(l3) << 16) | __bfloat16_as_ushort(l2);
    *(uint2*)&g_in_hi[idx * 4] = ph;
    *(uint2*)&g_in_lo[idx * 4] = pl;
}

__global__ void ut_split_kernel(const float* __restrict__ U) {
    const int d = blockIdx.x;
    for (int i = threadIdx.x; i < I_; i += 256) {
        float u = U[(size_t)i * D_ + d];
        __nv_bfloat16 h = __float2bfloat16(u);
        g_Ut_hi[(size_t)d * I_ + i] = h;
        g_Ut_lo[(size_t)d * I_ + i] = __float2bfloat16(u - __bfloat162float(h));
    }
}

__global__ void wt_split_kernel(const float* __restrict__ W) {
    const int n = blockIdx.x;
    for (int k = threadIdx.x; k < D_; k += 256) {
        float w = W[(size_t)k * D_ + n];
        __nv_bfloat16 h = __float2bfloat16(w);
        g_Wt_hi[(size_t)n * D_ + k] = h;
        g_Wt_lo[(size_t)n * D_ + k] = __float2bfloat16(w - __bfloat162float(h));
    }
}

// ---------------------------------------------------------------------------
// SMEM layout: bf16 rows of 128 elems, stride 68 words (conflict-free)
// ---------------------------------------------------------------------------
#define SROW 68
#define A_HI_W 0
#define A_LO_W (128 * SROW)
#define B_HI_W (256 * SROW)
#define B_LO_W (320 * SROW)
#define SMEM_BYTES (384 * SROW * 4)   // 104448 B

// ---------------------------------------------------------------------------
// Embed (tensor core): E[t][b][:] = inp[b,t,:] @ U / 16 + bias
// ---------------------------------------------------------------------------
__global__ void __launch_bounds__(NTHREADS, 1) embed_mma_kernel(
        const float* __restrict__ bias) {
    extern __shared__ __align__(16) uint32_t smw[];
    const int tid = threadIdx.x;
    const int wid = tid >> 5;
    const int lt  = tid & 31;
    const int g4  = lt >> 2;
    const int q4  = lt & 3;
    const int nb  = blockIdx.x;
    const int mt_idx = blockIdx.y;
    const int n0  = nb * NTILE;
    const int b   = mt_idx >> 2;
    const int t0  = (mt_idx & 3) << 7;
    const size_t row0 = (size_t)b * T_ + t0;

    const int w_m = wid >> 1;
    const int w_n = wid & 1;
    const int m_base = w_m * 32;
    const int n_base = w_n * 32;

    const int a_r  = lt & 15;
    const int a_cw = ((lt >> 4) & 1) * 4;
    const int b_r  = ((lt >> 4) & 1) * 8 + (lt & 7);
    const int b_cw = ((lt >> 3) & 1) * 4;

    uint32_t smem_b32 = (uint32_t)__cvta_generic_to_shared(smw);

    float acc[2][4][4];
    #pragma unroll
    for (int mt = 0; mt < 2; mt++)
        #pragma unroll
        for (int nt = 0; nt < 4; nt++)
            #pragma unroll
            for (int j = 0; j < 4; j++) acc[mt][nt][j] = 0.f;

    for (int chunk = 0; chunk < 2; chunk++) {
        const int i0 = chunk * 128;
        __syncthreads();
        #pragma unroll
        for (int hl = 0; hl < 2; hl++) {
            const __nv_bfloat16* src = hl ? g_in_lo : g_in_hi;
            const int base_w = hl ? A_LO_W : A_HI_W;
            #pragma unroll
            for (int i = 0; i < 8; i++) {
                int idx = i * 256 + tid;
                int r   = idx >> 4;
                int ch  = idx & 15;
                uint32_t dst = smem_b32 + (base_w + r * SROW + ch * 4) * 4;
                const char* g = (const char*)(src + (row0 + r) * I_ + i0) + ch * 16;
                asm volatile("cp.async.cg.shared.global [%0], [%1], 16;\n" :: "r"(dst), "l"(g));
            }
        }
        #pragma unroll
        for (int hl = 0; hl < 2; hl++) {
            const __nv_bfloat16* src = hl ? g_Ut_lo : g_Ut_hi;
            const int base_w = hl ? B_LO_W : B_HI_W;
            #pragma unroll
            for (int i = 0; i < 4; i++) {
                int idx = i * 256 + tid;
                int r   = idx >> 4;
                int ch  = idx & 15;
                uint32_t dst = smem_b32 + (base_w + r * SROW + ch * 4) * 4;
                const char* g = (const char*)(src + (size_t)(n0 + r) * I_ + i0) + ch * 16;
                asm volatile("cp.async.cg.shared.global [%0], [%1], 16;\n" :: "r"(dst), "l"(g));
            }
        }
        asm volatile("cp.async.commit_group;\n");
        asm volatile("cp.async.wait_group 0;\n");
        __syncthreads();

        #pragma unroll 2
        for (int kc = 0; kc < 8; kc++) {
            const int kw = kc * 8;
            uint32_t a_hi[2][4], a_lo[2][4], b_hi[2][4], b_lo[2][4];
            #pragma unroll
            for (int mt = 0; mt < 2; mt++) {
                int row = m_base + mt * 16 + a_r;
                ldm_x4(a_hi[mt], smem_b32 + (A_HI_W + row * SROW + kw + a_cw) * 4);
                ldm_x4(a_lo[mt], smem_b32 + (A_LO_W + row * SROW + kw + a_cw) * 4);
            }
            #pragma unroll
            for (int np = 0; np < 2; np++) {
                int row = n_base + np * 16 + b_r;
                ldm_x4(b_hi[np], smem_b32 + (B_HI_W + row * SROW + kw + b_cw) * 4);
                ldm_x4(b_lo[np], smem_b32 + (B_LO_W + row * SROW + kw + b_cw) * 4);
            }
            #pragma unroll
            for (int mt = 0; mt < 2; mt++)
                #pragma unroll
                for (int np = 0; np < 2; np++)
                    #pragma unroll
                    for (int h = 0; h < 2; h++) {
                        mma_bf16(acc[mt][np * 2 + h], a_hi[mt], &b_hi[np][h * 2]);
                        mma_bf16(acc[mt][np * 2 + h], a_hi[mt], &b_lo[np][h * 2]);
                        mma_bf16(acc[mt][np * 2 + h], a_lo[mt], &b_hi[np][h * 2]);
                    }
        }
    }

    const float inv16 = 0.0625f;
    #pragma unroll
    for (int nt = 0; nt < 4; nt++) {
        const int C = n0 + n_base + nt * 8 + q4 * 2;
        float2 bv = *(const float2*)&bias[C];
        #pragma unroll
        for (int mt = 0; mt < 2; mt++) {
            const int R = m_base + mt * 16 + g4;
            float2 o0 = make_float2(acc[mt][nt][0] * inv16 + bv.x,
                                    acc[mt][nt][1] * inv16 + bv.y);
            float2 o1 = make_float2(acc[mt][nt][2] * inv16 + bv.x,
                                    acc[mt][nt][3] * inv16 + bv.y);
            *(float2*)&g_E[((size_t)(t0 + R) * B_ + b) * D_ + C]     = o0;
            *(float2*)&g_E[((size_t)(t0 + R + 8) * B_ + b) * D_ + C] = o1;
        }
    }
}

// ---------------------------------------------------------------------------
// s_0 = erf(E_first), split into bf16 hi/lo
// ---------------------------------------------------------------------------
__global__ void s0_kernel() {
    int idx = blockIdx.x * blockDim.x + threadIdx.x;
    int m = idx >> 10;
    int d = idx & 1023;
    float e = (m < B_) ? g_E[(size_t)0 * (B_ * D_) + m * D_ + d]
                       : g_E[(size_t)(T_ - 1) * (B_ * D_) + (m - B_) * D_ + d];
    float s = erff(e);
    __nv_bfloat16 h = __float2bfloat16(s);
    g_s_hi[idx] = h;
    g_s_lo[idx] = __float2bfloat16(s - __bfloat162float(h));
}

// ---------------------------------------------------------------------------
// Persistent recurrence kernel: 511 steps, group-local barriers.
// grid = 128 CTAs: (nb 0..15) x (kb 0..7).  Group g = 16 CTAs sharing kb.
//   barrier1: partials [*][cols kb*128..+128) written by CTAs with nb>>1==kb
//             -> arrive c1[nb>>1], wait c1[kb]
//   reduce:   CTA (nb,kb) reduces rows [nb*8, nb*8+8) x cols [kb*128,+128)
//   barrier2: s slice kb complete -> 16-CTA barrier on c2[kb]
// ---------------------------------------------------------------------------
__global__ void __launch_bounds__(NTHREADS, 1) rnn_kernel() {
    extern __shared__ __align__(16) uint32_t smw[];
    const int tid = threadIdx.x;
    const int wid = tid >> 5;
    const int lt  = tid & 31;
    const int g4  = lt >> 2;
    const int q4  = lt & 3;
    const int bid = blockIdx.x;
    const int nb  = bid & 15;
    const int kb  = bid >> 4;
    const int n0  = nb * NTILE;
    const int k0  = kb * KSLICE;

    const int w_m = wid >> 1;
    const int w_n = wid & 1;
    const int m_base = w_m * 32;
    const int n_base = w_n * 32;

    const int a_r  = lt & 15;
    const int a_cw = ((lt >> 4) & 1) * 4;
    const int b_r  = ((lt >> 4) & 1) * 8 + (lt & 7);
    const int b_cw = ((lt >> 3) & 1) * 4;

    uint32_t smem_b32 = (uint32_t)__cvta_generic_to_shared(smw);

    // ---- Preload B = W^T slices (constant across all steps) ----
    #pragma unroll
    for (int hl = 0; hl < 2; hl++) {
        const __nv_bfloat16* src = hl ? g_Wt_lo : g_Wt_hi;
        const int base_w = hl ? B_LO_W : B_HI_W;
        #pragma unroll
        for (int i = 0; i < 4; i++) {
            int idx = i * 256 + tid;
            int r   = idx >> 4;
            int ch  = idx & 15;
            uint32_t dst = smem_b32 + (base_w + r * SROW + ch * 4) * 4;
            const char* g = (const char*)(src + (size_t)(n0 + r) * D_ + k0) + ch * 16;
            asm volatile("cp.async.cg.shared.global [%0], [%1], 16;\n" :: "r"(dst), "l"(g));
        }
    }
    asm volatile("cp.async.commit_group;\n");
    asm volatile("cp.async.wait_group 0;\n");
    __syncthreads();

    // precomputed ldmatrix byte addresses
    uint32_t aaddr_hi[2], aaddr_lo[2], baddr_hi[2], baddr_lo[2];
    #pragma unroll
    for (int mt = 0; mt < 2; mt++) {
        int row = m_base + mt * 16 + a_r;
        aaddr_hi[mt] = smem_b32 + (A_HI_W + row * SROW + a_cw) * 4;
        aaddr_lo[mt] = smem_b32 + (A_LO_W + row * SROW + a_cw) * 4;
    }
    #pragma unroll
    for (int np = 0; np < 2; np++) {
        int row = n_base + np * 16 + b_r;
        baddr_hi[np] = smem_b32 + (B_HI_W + row * SROW + b_cw) * 4;
        baddr_lo[np] = smem_b32 + (B_LO_W + row * SROW + b_cw) * 4;
    }

    // group-local reduce assignment:
    // rows [nb*8, nb*8+8), cols [kb*128,+128); 4 consecutive elems per thread
    const int r_m   = nb * 8 + (tid >> 5);
    const int r_d   = k0 + (tid & 31) * 4;
    const bool r_fwd = (r_m < B_);
    const int r_mm  = r_fwd ? r_m : (r_m - B_);

    unsigned* const arr1 = &g_c1[(nb >> 1) * 32];   // arrive here (barrier 1)
    unsigned* const wat1 = &g_c1[kb * 32];          // wait here   (barrier 1)
    unsigned* const bar2 = &g_c2[kb * 32];          // group barrier 2

    for (int t = 0; t < T_ - 1; t++) {
        // ---- Load A tiles: s_hi / s_lo slices [128 x 128 bf16] (L1-bypass) ----
        #pragma unroll
        for (int hl = 0; hl < 2; hl++) {
            const __nv_bfloat16* src = hl ? g_s_lo : g_s_hi;
            const int base_w = hl ? A_LO_W : A_HI_W;
            #pragma unroll
            for (int i = 0; i < 8; i++) {
                int idx = i * 256 + tid;
                int r   = idx >> 4;
                int ch  = idx & 15;
                uint32_t dst = smem_b32 + (base_w + r * SROW + ch * 4) * 4;
                const char* g = (const char*)(src + (size_t)r * D_ + k0) + ch * 16;
                asm volatile("cp.async.cg.shared.global [%0], [%1], 16;\n" :: "r"(dst), "l"(g));
            }
        }
        asm volatile("cp.async.commit_group;\n");

        // ---- Prefetch E for this step's reduce share ----
        const int te = r_fwd ? (t + 1) : (T_ - 2 - t);
        const float4 e4 = *(const float4*)&g_E[((size_t)te * B_ + r_mm) * D_ + r_d];

        asm volatile("cp.async.wait_group 0;\n");
        __syncthreads();

        // ---- GEMM: C[32x32/warp] = A_hi*B_hi + A_hi*B_lo + A_lo*B_hi ----
        float acc[2][4][4];
        #pragma unroll
        for (int mt = 0; mt < 2; mt++)
            #pragma unroll
            for (int nt = 0; nt < 4; nt++)
                #pragma unroll
                for (int j = 0; j < 4; j++) acc[mt][nt][j] = 0.f;

        #pragma unroll 2
        for (int kc = 0; kc < 8; kc++) {
            const uint32_t koff = kc * 32;
            uint32_t a_hi[2][4], a_lo[2][4], b_hi[2][4], b_lo[2][4];
            #pragma unroll
            for (int mt = 0; mt < 2; mt++) {
                ldm_x4(a_hi[mt], aaddr_hi[mt] + koff);
                ldm_x4(a_lo[mt], aaddr_lo[mt] + koff);
            }
            #pragma unroll
            for (int np = 0; np < 2; np++) {
                ldm_x4(b_hi[np], baddr_hi[np] + koff);
                ldm_x4(b_lo[np], baddr_lo[np] + koff);
            }
            #pragma unroll
            for (int mt = 0; mt < 2; mt++)
                #pragma unroll
                for (int np = 0; np < 2; np++)
                    #pragma unroll
                    for (int h = 0; h < 2; h++) {
                        mma_bf16(acc[mt][np * 2 + h], a_hi[mt], &b_hi[np][h * 2]);
                        mma_bf16(acc[mt][np * 2 + h], a_hi[mt], &b_lo[np][h * 2]);
                        mma_bf16(acc[mt][np * 2 + h], a_lo[mt], &b_hi[np][h * 2]);
                    }
        }

        // ---- Write split-K partials ----
        #pragma unroll
        for (int mt = 0; mt < 2; mt++) {
            const int R = m_base + mt * 16 + g4;
            #pragma unroll
            for (int nt = 0; nt < 4; nt++) {
                const int C = n0 + n_base + nt * 8 + q4 * 2;
                *(float2*)&g_part[kb][R][C]     = make_float2(acc[mt][nt][0], acc[mt][nt][1]);
                *(float2*)&g_part[kb][R + 8][C] = make_float2(acc[mt][nt][2], acc[mt][nt][3]);
            }
        }

        // ---- Barrier 1 (neighborhood): partials for my reduce cols ready ----
        __syncthreads();
        if (tid == 0) {
            asm volatile("red.release.gpu.global.add.u32 [%0], 1;"
                         :: "l"(arr1) : "memory");
            unsigned v;
            const unsigned tgt = 16u * (unsigned)(t + 1);
            do {
                asm volatile("ld.acquire.gpu.global.u32 %0, [%1];"
                             : "=r"(v) : "l"(wat1) : "memory");
            } while (v < tgt);
        }
        __syncthreads();

        // ---- Reduce (L2-direct loads): c = sum/32, s = erf(E + c), split ----
        {
            float4 sum = {0.f, 0.f, 0.f, 0.f};
            #pragma unroll
            for (int kk = 0; kk < KSPLIT; kk++) {
                float4 p = __ldcg((const float4*)&g_part[kk][r_m][r_d]);
                sum.x += p.x; sum.y += p.y; sum.z += p.z; sum.w += p.w;
            }
            const float inv32 = 0.03125f;
            float s0 = erff(e4.x + sum.x * inv32);
            float s1 = erff(e4.y + sum.y * inv32);
            float s2 = erff(e4.z + sum.z * inv32);
            float s3 = erff(e4.w + sum.w * inv32);

            __nv_bfloat16 h0 = __float2bfloat16(s0);
            __nv_bfloat16 h1 = __float2bfloat16(s1);
            __nv_bfloat16 h2 = __float2bfloat16(s2);
            __nv_bfloat16 h3 = __float2bfloat16(s3);
            __nv_bfloat16 l0 = __float2bfloat16(s0 - __bfloat162float(h0));
            __nv_bfloat16 l1 = __float2bfloat16(s1 - __bfloat162float(h1));
            __nv_bfloat16 l2 = __float2bfloat16(s2 - __bfloat162float(h2));
            __nv_bfloat16 l3 = __float2bfloat16(s3 - __bfloat162float(h3));

            uint2 ph, pl;
            ph.x = ((uint32_t)__bfloat16_as_ushort(h1) << 16) | __bfloat16_as_ushort(h0);
            ph.y = ((uint32_t)__bfloat16_as_ushort(h3) << 16) | __bfloat16_as_ushort(h2);
            pl.x = ((uint32_t)__bfloat16_as_ushort(l1) << 16) | __bfloat16_as_ushort(l0);
            pl.y = ((uint32_t)__bfloat16_as_ushort(l3) << 16) | __bfloat16_as_ushort(l2);
            *(uint2*)&g_s_hi[(size_t)r_m * D_ + r_d] = ph;
            *(uint2*)&g_s_lo[(size_t)r_m * D_ + r_d] = pl;
        }

        // ---- Barrier 2 (group of 16): s slice kb complete ----
        __syncthreads();
        if (tid == 0) {
            asm volatile("red.release.gpu.global.add.u32 [%0], 1;"
                         :: "l"(bar2) : "memory");
            unsigned v;
            const unsigned tgt = 16u * (unsigned)(t + 1);
            do {
                asm volatile("ld.acquire.gpu.global.u32 %0, [%1];"
                             : "=r"(v) : "l"(bar2) : "memory");
            } while (v < tgt);
        }
        __syncthreads();
    }
}

// ---------------------------------------------------------------------------
// Output head
// ---------------------------------------------------------------------------
__global__ void out_kernel(const float* __restrict__ v, float* __restrict__ out) {
    const int b   = blockIdx.x;
    const int tid = threadIdx.x;
    float sum = 0.f;
    for (int d = tid; d < D_; d += 256) {
        float sf = __bfloat162float(g_s_hi[b * D_ + d]) + __bfloat162float(g_s_lo[b * D_ + d]);
        float sb = __bfloat162float(g_s_hi[(B_ + b) * D_ + d]) + __bfloat162float(g_s_lo[(B_ + b) * D_ + d]);
        sum += sf * v[d] + sb * v[D_ + d];
    }
    __shared__ float red[256];
    red[tid] = sum;
    __syncthreads();
    #pragma unroll
    for (int s = 128; s > 0; s >>= 1) {
        if (tid < s) red[tid] += red[tid + s];
        __syncthreads();
    }
    if (tid == 0) out[b] = red[0] * 0.03125f;
}

// ---------------------------------------------------------------------------
// kernel_launch: graph-capturable (kernel launches only)
// ---------------------------------------------------------------------------
extern "C" void kernel_launch(void* const* d_in, const int* in_sizes, int n_in,
                              void* d_out, int out_size) {
    const float* inp  = (const float*)d_in[0];
    const float* W    = (const float*)d_in[1];
    const float* U    = (const float*)d_in[2];
    const float* bias = (const float*)d_in[3];
    const float* v    = (const float*)d_in[4];
    float* out        = (float*)d_out;

    static bool attr_set = false;
    if (!attr_set) {
        cudaFuncSetAttribute(rnn_kernel, cudaFuncAttributeMaxDynamicSharedMemorySize, SMEM_BYTES);
        cudaFuncSetAttribute(embed_mma_kernel, cudaFuncAttributeMaxDynamicSharedMemorySize, SMEM_BYTES);
        attr_set = true;
    }

    zero_bar_kernel<<<1, 256>>>();
    inp_split_kernel<<<(B_ * T_ * I_ / 4 + 255) / 256, 256>>>(inp);
    ut_split_kernel<<<D_, 256>>>(U);
    wt_split_kernel<<<D_, 256>>>(W);
    embed_mma_kernel<<<dim3(16, 256), NTHREADS, SMEM_BYTES>>>(bias);
    s0_kernel<<<512, 256>>>();
    rnn_kernel<<<NCTA, NTHREADS, SMEM_BYTES>>>();
    out_kernel<<<B_, 256>>>(v, out);
}